// round 1
// baseline (speedup 1.0000x reference)
#include <cuda_runtime.h>
#include <math.h>

#define D_MODEL 1024
#define N_HEADS 16
#define HEAD_DIM 64
#define B_SZ 2
#define SEQ 2048
#define M_TOT (B_SZ * SEQ)   // 4096

// Scratch (allocation-free rule: device globals)
__device__ float g_Q[(size_t)M_TOT * D_MODEL];
__device__ float g_K[(size_t)M_TOT * D_MODEL];
__device__ float g_V[(size_t)M_TOT * D_MODEL];
__device__ float g_A[(size_t)M_TOT * D_MODEL];

// ---------------------------------------------------------------------------
// SGEMM + bias: C[M,N] = A[M,K] @ B[K,N] + bias[N]
// 128x128x8 block, 8x8 per thread, 256 threads.
// ---------------------------------------------------------------------------
__global__ __launch_bounds__(256, 2)
void sgemm_bias(const float* __restrict__ A, const float* __restrict__ Bm,
                const float* __restrict__ bias, float* __restrict__ C,
                int M, int N, int K)
{
    __shared__ float As[8][128];
    __shared__ float Bs[8][128];

    const int bx = blockIdx.x, by = blockIdx.y;
    const int tid = threadIdx.x;
    const int tx = tid & 15, ty = tid >> 4;

    const float* Ab = A + (size_t)(by * 128) * K;
    const float* Bb = Bm + bx * 128;

    const int aRow = tid >> 1;          // 0..127
    const int aCol = (tid & 1) << 2;    // 0 or 4
    const int bRow = tid >> 5;          // 0..7
    const int bCol = (tid & 31) << 2;   // 0..124

    float acc[8][8];
    #pragma unroll
    for (int i = 0; i < 8; i++)
        #pragma unroll
        for (int j = 0; j < 8; j++) acc[i][j] = 0.f;

    for (int k0 = 0; k0 < K; k0 += 8) {
        float4 av = *(const float4*)(Ab + (size_t)aRow * K + k0 + aCol);
        As[aCol + 0][aRow] = av.x;
        As[aCol + 1][aRow] = av.y;
        As[aCol + 2][aRow] = av.z;
        As[aCol + 3][aRow] = av.w;
        float4 bv = *(const float4*)(Bb + (size_t)(k0 + bRow) * N + bCol);
        *(float4*)&Bs[bRow][bCol] = bv;
        __syncthreads();

        #pragma unroll
        for (int k = 0; k < 8; k++) {
            float a0[8], b0[8];
            *(float4*)&a0[0] = *(float4*)&As[k][ty * 4];
            *(float4*)&a0[4] = *(float4*)&As[k][64 + ty * 4];
            *(float4*)&b0[0] = *(float4*)&Bs[k][tx * 4];
            *(float4*)&b0[4] = *(float4*)&Bs[k][64 + tx * 4];
            #pragma unroll
            for (int i = 0; i < 8; i++)
                #pragma unroll
                for (int j = 0; j < 8; j++)
                    acc[i][j] += a0[i] * b0[j];
        }
        __syncthreads();
    }

    // Epilogue: bias + store (rows: ty*4+i / 64+ty*4+i-4 ; cols: tx*4 / 64+tx*4)
    #pragma unroll
    for (int i = 0; i < 8; i++) {
        int row = by * 128 + ((i < 4) ? (ty * 4 + i) : (64 + ty * 4 + i - 4));
        int c0 = bx * 128 + tx * 4;
        int c1 = c0 + 64;
        float4 v0, v1;
        v0.x = acc[i][0] + bias[c0 + 0];
        v0.y = acc[i][1] + bias[c0 + 1];
        v0.z = acc[i][2] + bias[c0 + 2];
        v0.w = acc[i][3] + bias[c0 + 3];
        v1.x = acc[i][4] + bias[c1 + 0];
        v1.y = acc[i][5] + bias[c1 + 1];
        v1.z = acc[i][6] + bias[c1 + 2];
        v1.w = acc[i][7] + bias[c1 + 3];
        *(float4*)&C[(size_t)row * N + c0] = v0;
        *(float4*)&C[(size_t)row * N + c1] = v1;
    }
}

// ---------------------------------------------------------------------------
// Flash-style attention, fp32. One block = one (b,h,64-row q-tile).
// 256 threads as 16x16; each thread: 4 S-rows (ty*4+i) x 4 S-cols (tx+16j),
// output dims tx*4+j. KV tiles of 64 keys, online softmax.
// ---------------------------------------------------------------------------
#define ST 68   // smem row stride in floats (64 + 4 pad)

__global__ __launch_bounds__(256, 2)
void attn_kernel(const float* __restrict__ Qg, const float* __restrict__ Kg,
                 const float* __restrict__ Vg, float* __restrict__ Og)
{
    extern __shared__ float sm[];
    float* Qs = sm;                // 64 x ST
    float* Ks = Qs + 64 * ST;
    float* Vs = Ks + 64 * ST;
    float* Ps = Vs + 64 * ST;

    const int qt = blockIdx.x;
    const int bh = blockIdx.y;
    const int b = bh >> 4, h = bh & 15;

    const int tid = threadIdx.x;
    const int tx = tid & 15, ty = tid >> 4;

    const float scale = 0.125f;  // 1/sqrt(64)

    const float* Qp = Qg + (size_t)(b * SEQ + qt * 64) * D_MODEL + h * HEAD_DIM;
    const float* Kp = Kg + (size_t)(b * SEQ) * D_MODEL + h * HEAD_DIM;
    const float* Vp = Vg + (size_t)(b * SEQ) * D_MODEL + h * HEAD_DIM;

    // Load Q tile (scaled)
    for (int i = tid; i < 64 * 16; i += 256) {
        int r = i >> 4, c = (i & 15) << 2;
        float4 v = *(const float4*)(Qp + (size_t)r * D_MODEL + c);
        v.x *= scale; v.y *= scale; v.z *= scale; v.w *= scale;
        *(float4*)&Qs[r * ST + c] = v;
    }

    float m[4], l[4], o[4][4];
    #pragma unroll
    for (int i = 0; i < 4; i++) {
        m[i] = -1e30f; l[i] = 0.f;
        #pragma unroll
        for (int j = 0; j < 4; j++) o[i][j] = 0.f;
    }

    for (int kt = 0; kt < SEQ / 64; kt++) {
        const float* Kt = Kp + (size_t)kt * 64 * D_MODEL;
        const float* Vt = Vp + (size_t)kt * 64 * D_MODEL;
        for (int i = tid; i < 64 * 16; i += 256) {
            int r = i >> 4, c = (i & 15) << 2;
            *(float4*)&Ks[r * ST + c] = *(const float4*)(Kt + (size_t)r * D_MODEL + c);
            *(float4*)&Vs[r * ST + c] = *(const float4*)(Vt + (size_t)r * D_MODEL + c);
        }
        __syncthreads();

        // S = (scaled Q) @ K^T ; cols strided (tx + 16j) for conflict-free Ks reads
        float s[4][4];
        #pragma unroll
        for (int i = 0; i < 4; i++)
            #pragma unroll
            for (int j = 0; j < 4; j++) s[i][j] = 0.f;

        #pragma unroll
        for (int d = 0; d < 64; d += 4) {
            float4 q4[4], k4[4];
            #pragma unroll
            for (int i = 0; i < 4; i++) q4[i] = *(float4*)&Qs[(ty * 4 + i) * ST + d];
            #pragma unroll
            for (int j = 0; j < 4; j++) k4[j] = *(float4*)&Ks[(tx + 16 * j) * ST + d];
            #pragma unroll
            for (int i = 0; i < 4; i++)
                #pragma unroll
                for (int j = 0; j < 4; j++)
                    s[i][j] += q4[i].x * k4[j].x + q4[i].y * k4[j].y
                             + q4[i].z * k4[j].z + q4[i].w * k4[j].w;
        }

        // Online softmax (width-16 butterfly over the row's 16 lanes)
        #pragma unroll
        for (int i = 0; i < 4; i++) {
            float rmax = s[i][0];
            #pragma unroll
            for (int j = 1; j < 4; j++) rmax = fmaxf(rmax, s[i][j]);
            #pragma unroll
            for (int off = 8; off > 0; off >>= 1)
                rmax = fmaxf(rmax, __shfl_xor_sync(0xffffffffu, rmax, off, 16));

            float mnew = fmaxf(m[i], rmax);
            float corr = __expf(m[i] - mnew);
            float rsum = 0.f;
            #pragma unroll
            for (int j = 0; j < 4; j++) {
                float p = __expf(s[i][j] - mnew);
                Ps[(ty * 4 + i) * ST + tx + 16 * j] = p;
                rsum += p;
            }
            #pragma unroll
            for (int off = 8; off > 0; off >>= 1)
                rsum += __shfl_xor_sync(0xffffffffu, rsum, off, 16);

            l[i] = l[i] * corr + rsum;
            m[i] = mnew;
            #pragma unroll
            for (int j = 0; j < 4; j++) o[i][j] *= corr;
        }
        __syncwarp();   // Ps row-group is intra-warp: warp sync suffices

        // O += P @ V (output dims tx*4..tx*4+3)
        #pragma unroll
        for (int c0 = 0; c0 < 64; c0 += 4) {
            float4 p4[4];
            #pragma unroll
            for (int i = 0; i < 4; i++) p4[i] = *(float4*)&Ps[(ty * 4 + i) * ST + c0];
            #pragma unroll
            for (int cc = 0; cc < 4; cc++) {
                float4 vv = *(float4*)&Vs[(c0 + cc) * ST + tx * 4];
                #pragma unroll
                for (int i = 0; i < 4; i++) {
                    float p = (cc == 0) ? p4[i].x : (cc == 1) ? p4[i].y
                             : (cc == 2) ? p4[i].z : p4[i].w;
                    o[i][0] += p * vv.x;
                    o[i][1] += p * vv.y;
                    o[i][2] += p * vv.z;
                    o[i][3] += p * vv.w;
                }
            }
        }
        __syncthreads();  // protect Ks/Vs before next tile load
    }

    // Normalize + store to [B, L, D] with heads interleaved at h*64
    float* Op = Og + (size_t)(b * SEQ + qt * 64) * D_MODEL + h * HEAD_DIM;
    #pragma unroll
    for (int i = 0; i < 4; i++) {
        float inv = 1.0f / l[i];
        float4 v;
        v.x = o[i][0] * inv; v.y = o[i][1] * inv;
        v.z = o[i][2] * inv; v.w = o[i][3] * inv;
        *(float4*)(Op + (size_t)(ty * 4 + i) * D_MODEL + tx * 4) = v;
    }
}

// ---------------------------------------------------------------------------
extern "C" void kernel_launch(void* const* d_in, const int* in_sizes, int n_in,
                              void* d_out, int out_size)
{
    const float* query = (const float*)d_in[0];
    const float* key   = (const float*)d_in[1];
    const float* value = (const float*)d_in[2];
    const float* Wq    = (const float*)d_in[3];
    const float* bq    = (const float*)d_in[4];
    const float* Wk    = (const float*)d_in[5];
    const float* bk    = (const float*)d_in[6];
    const float* Wv    = (const float*)d_in[7];
    const float* bv    = (const float*)d_in[8];
    const float* Wo    = (const float*)d_in[9];
    const float* bo    = (const float*)d_in[10];
    float* out = (float*)d_out;

    float *Qb, *Kb, *Vb, *Ab;
    cudaGetSymbolAddress((void**)&Qb, g_Q);
    cudaGetSymbolAddress((void**)&Kb, g_K);
    cudaGetSymbolAddress((void**)&Vb, g_V);
    cudaGetSymbolAddress((void**)&Ab, g_A);

    dim3 gg(D_MODEL / 128, M_TOT / 128);   // (8, 32)

    sgemm_bias<<<gg, 256>>>(query, Wq, bq, Qb, M_TOT, D_MODEL, D_MODEL);
    sgemm_bias<<<gg, 256>>>(key,   Wk, bk, Kb, M_TOT, D_MODEL, D_MODEL);
    sgemm_bias<<<gg, 256>>>(value, Wv, bv, Vb, M_TOT, D_MODEL, D_MODEL);

    size_t smem = (size_t)4 * 64 * ST * sizeof(float);  // 69632 B
    cudaFuncSetAttribute(attn_kernel,
                         cudaFuncAttributeMaxDynamicSharedMemorySize, (int)smem);
    attn_kernel<<<dim3(SEQ / 64, B_SZ * N_HEADS), 256, smem>>>(Qb, Kb, Vb, Ab);

    sgemm_bias<<<gg, 256>>>(Ab, Wo, bo, out, M_TOT, D_MODEL, D_MODEL);
}